// round 13
// baseline (speedup 1.0000x reference)
#include <cuda_runtime.h>
#include <cuda_fp16.h>
#include <cstdint>

// Problem constants: N=100000, F=512, H=16, C=40, E=3200000
#define NMAX 100000
#define EMAX 3200000
#define FDIM 512
#define HDIM 16
#define CDIM 40

// ---- scratch (static device globals; no allocation allowed) ----
__device__ int    g_is64;
__device__ int2   g_edge[EMAX];      // (src, dst)
__device__ int    g_deg[NMAX];
__device__ float2 g_hraw[NMAX * 8];  // fp32 raw x@W1 (pre-scale)
__device__ uint4  g_h   [NMAX * 2];  // fp16 scaled hidden L1 (gather table)
__device__ uint4  g_h2  [NMAX * 2];  // fp16 scaled hidden L2 (gather table)
__device__ uint4  g_agg1[NMAX * 2];  // fp16 accumulator L1 (init = g_h row)
__device__ uint4  g_agg2[NMAX * 2];  // fp16 accumulator L2 (init = g_h2 row)

// ---- f32x2 packed-math helpers (sm_103a) ----
__device__ __forceinline__ unsigned long long f2_fma(
    unsigned long long a, unsigned long long b, unsigned long long c) {
    unsigned long long d;
    asm("fma.rn.f32x2 %0, %1, %2, %3;" : "=l"(d) : "l"(a), "l"(b), "l"(c));
    return d;
}
__device__ __forceinline__ unsigned long long f2_add(
    unsigned long long a, unsigned long long b) {
    unsigned long long d;
    asm("add.rn.f32x2 %0, %1, %2;" : "=l"(d) : "l"(a), "l"(b));
    return d;
}
__device__ __forceinline__ unsigned long long f2_pack(float lo, float hi) {
    unsigned long long d;
    asm("mov.b64 %0, {%1, %2};" : "=l"(d) : "f"(lo), "f"(hi));
    return d;
}

// ---------------------------------------------------------------
__global__ void k_init(const int* __restrict__ ei, int N) {
    int i = blockIdx.x * blockDim.x + threadIdx.x;
    if (i < N) g_deg[i] = 0;
    if (i == 0) {
        int any = 0;
        #pragma unroll
        for (int q = 1; q < 256; q += 2) any |= ei[q];
        g_is64 = (any == 0) ? 1 : 0;
    }
}

// Normalize edges to packed int2 and count in-degree (dst side).
__global__ __launch_bounds__(256) void k_convert(const void* __restrict__ ei, int E) {
    int e = blockIdx.x * blockDim.x + threadIdx.x;
    if (e >= E) return;
    int s, d;
    if (g_is64) {
        const long long* p = (const long long*)ei;
        s = (int)p[e];
        d = (int)p[(long long)E + e];
    } else {
        const int* p = (const int*)ei;
        s = p[e];
        d = p[E + e];
    }
    g_edge[e] = make_int2(s, d);
    atomicAdd(&g_deg[d], 1);
}

// ---------------------------------------------------------------
// GEMM1 (raw): g_hraw[i,:] = x[i,:] @ W1.
// FROZEN R10 config (proven local optimum): 8 warps/block, 4 rows/warp,
// scalar coalesced x loads, f32x2 accumulators, W1 in shared as float2
// j-pairs with odd pitch, value-halving butterfly tail into a separate
// register array, launch_bounds(256,2).
#define WPITCH 513
__global__ __launch_bounds__(256, 2) void k_gemm1raw(
    const float* __restrict__ x, const float* __restrict__ W1, int N)
{
    __shared__ unsigned long long wS[8 * WPITCH];
    {
        const unsigned long long* gw = (const unsigned long long*)W1;
        for (int idx = threadIdx.x; idx < FDIM * 8; idx += 256) {
            int k = idx >> 3, j2 = idx & 7;
            wS[j2 * WPITCH + k] = gw[idx];
        }
    }
    __syncthreads();

    int warp = threadIdx.x >> 5;
    int lane = threadIdx.x & 31;
    int r0 = blockIdx.x * 32 + warp * 4;

    unsigned long long acc[4][8];
    #pragma unroll
    for (int r = 0; r < 4; r++)
        #pragma unroll
        for (int j = 0; j < 8; j++) acc[r][j] = 0ull;

    bool v0 = (r0 + 0) < N, v1 = (r0 + 1) < N, v2 = (r0 + 2) < N, v3 = (r0 + 3) < N;
    const float* x0p = x + (size_t)(r0 + 0) * FDIM + lane;
    const float* x1p = x + (size_t)(r0 + 1) * FDIM + lane;
    const float* x2p = x + (size_t)(r0 + 2) * FDIM + lane;
    const float* x3p = x + (size_t)(r0 + 3) * FDIM + lane;

    #pragma unroll 4
    for (int i = 0; i < 16; i++) {
        int k = lane + 32 * i;
        float x0 = v0 ? x0p[32 * i] : 0.0f;
        float x1 = v1 ? x1p[32 * i] : 0.0f;
        float x2 = v2 ? x2p[32 * i] : 0.0f;
        float x3 = v3 ? x3p[32 * i] : 0.0f;
        unsigned long long p0 = f2_pack(x0, x0);
        unsigned long long p1 = f2_pack(x1, x1);
        unsigned long long p2 = f2_pack(x2, x2);
        unsigned long long p3 = f2_pack(x3, x3);
        #pragma unroll
        for (int j = 0; j < 8; j++) {
            unsigned long long wv = wS[j * WPITCH + k];
            acc[0][j] = f2_fma(p0, wv, acc[0][j]);
            acc[1][j] = f2_fma(p1, wv, acc[1][j]);
            acc[2][j] = f2_fma(p2, wv, acc[2][j]);
            acc[3][j] = f2_fma(p3, wv, acc[3][j]);
        }
    }

    unsigned long long v[32];
    #pragma unroll
    for (int r = 0; r < 4; r++)
        #pragma unroll
        for (int j = 0; j < 8; j++) v[r * 8 + j] = acc[r][j];

    #pragma unroll
    for (int s = 0; s < 5; s++) {
        const int m = 1 << s;
        const int half = 16 >> s;
        bool up = (lane & m) != 0;
        #pragma unroll
        for (int q = 0; q < 16; q++) {
            if (q < half) {
                unsigned long long keep = up ? v[q + half] : v[q];
                unsigned long long mine = up ? v[q] : v[q + half];
                unsigned long long got = __shfl_xor_sync(0xffffffffu, mine, m);
                v[q] = f2_add(keep, got);
            }
        }
    }

    int p = ((lane & 1) << 4) | ((lane & 2) << 2) | (lane & 4) |
            ((lane & 8) >> 2) | ((lane & 16) >> 4);
    int r = p >> 3, j2 = p & 7;
    int row = r0 + r;
    if (row < N) {
        ((unsigned long long*)g_hraw)[(size_t)row * 8 + j2] = v[0];
    }
}

// ---------------------------------------------------------------
// Scale epilogue (after join): hs = fp16(dinv * hraw), dinv computed
// inline from deg. Writes gather table g_h and accumulator init g_agg1.
__global__ void k_scale(int N) {
    int idx = blockIdx.x * blockDim.x + threadIdx.x;   // half2 index
    if (idx >= N * 8) return;
    int i = idx >> 3;
    float dv = rsqrtf((float)(g_deg[i] + 1));
    float2 rf = g_hraw[idx];
    rf.x *= dv; rf.y *= dv;
    __half2 hv = __float22half2_rn(rf);
    ((__half2*)g_h)[idx] = hv;
    ((__half2*)g_agg1)[idx] = hv;
}

// ---------------------------------------------------------------
// Edge propagation for ONE chunk c: one thread per edge. Gather the
// 16B chunk of the source row, one fp16x2 vector RED into dst chunk.
// (R10-proven memory shape; chunk c passed as a kernel arg so the two
// chunk pipelines run concurrently on separate streams.)
__global__ __launch_bounds__(256) void k_prop_c(int E, int layer, int c) {
    int e = blockIdx.x * blockDim.x + threadIdx.x;
    if (e >= E) return;
    const uint4* hin = layer ? g_h2 : g_h;
    uint4* out = layer ? g_agg2 : g_agg1;

    int2 sd = g_edge[e];
    uint4 v = hin[(size_t)sd.x * 2 + c];
    uint4* p = out + (size_t)sd.y * 2 + c;
    asm volatile("red.global.add.noftz.v4.f16x2 [%0], {%1, %2, %3, %4};"
                 :: "l"(p), "r"(v.x), "r"(v.y), "r"(v.z), "r"(v.w)
                 : "memory");
}

// ---------------------------------------------------------------
// Mid layer for ONE chunk c: out1 = relu(dinv*agg1 + b1); hs2 = dinv*out1
__global__ void k_mid_c(const float* __restrict__ b1, int N, int c) {
    int i = blockIdx.x * blockDim.x + threadIdx.x;
    if (i >= N) return;
    int idx = i * 2 + c;
    float dv = rsqrtf((float)(g_deg[i] + 1));
    uint4 a = g_agg1[idx];
    float2 f0 = __half22float2(*(__half2*)&a.x);
    float2 f1 = __half22float2(*(__half2*)&a.y);
    float2 f2v = __half22float2(*(__half2*)&a.z);
    float2 f3 = __half22float2(*(__half2*)&a.w);
    const float4* b4 = (const float4*)b1;
    float4 bb0 = b4[c * 2 + 0];
    float4 bb1 = b4[c * 2 + 1];
    float2 r0, r1, r2, r3;
    r0.x = fmaxf(dv * f0.x + bb0.x, 0.f) * dv;
    r0.y = fmaxf(dv * f0.y + bb0.y, 0.f) * dv;
    r1.x = fmaxf(dv * f1.x + bb0.z, 0.f) * dv;
    r1.y = fmaxf(dv * f1.y + bb0.w, 0.f) * dv;
    r2.x = fmaxf(dv * f2v.x + bb1.x, 0.f) * dv;
    r2.y = fmaxf(dv * f2v.y + bb1.y, 0.f) * dv;
    r3.x = fmaxf(dv * f3.x + bb1.z, 0.f) * dv;
    r3.y = fmaxf(dv * f3.y + bb1.w, 0.f) * dv;
    uint4 o;
    *(__half2*)&o.x = __float22half2_rn(r0);
    *(__half2*)&o.y = __float22half2_rn(r1);
    *(__half2*)&o.z = __float22half2_rn(r2);
    *(__half2*)&o.w = __float22half2_rn(r3);
    g_h2[idx] = o;
    g_agg2[idx] = o;
}

// ---------------------------------------------------------------
// Output: logits = (dinv[i]*agg2[i,:]) @ W2 + b2 ; out = softmax
// d_out[0:N*40) = softmax ; d_out[N*40:2N*40) = logits
__global__ __launch_bounds__(256) void k_out(
    const float* __restrict__ W2, const float* __restrict__ b2,
    float* __restrict__ dout, int N, int write_h)
{
    __shared__ float w[HDIM * CDIM];
    __shared__ float bs[CDIM];
    for (int i = threadIdx.x; i < HDIM * CDIM; i += blockDim.x) w[i] = W2[i];
    if (threadIdx.x < CDIM) bs[threadIdx.x] = b2[threadIdx.x];
    __syncthreads();

    int i = blockIdx.x * blockDim.x + threadIdx.x;
    if (i >= N) return;

    float dv = rsqrtf((float)(g_deg[i] + 1));
    float row[HDIM];
    #pragma unroll
    for (int c = 0; c < 2; c++) {
        uint4 a = g_agg2[(size_t)i * 2 + c];
        float2 f0 = __half22float2(*(__half2*)&a.x);
        float2 f1 = __half22float2(*(__half2*)&a.y);
        float2 f2v = __half22float2(*(__half2*)&a.z);
        float2 f3 = __half22float2(*(__half2*)&a.w);
        row[c * 8 + 0] = f0.x * dv; row[c * 8 + 1] = f0.y * dv;
        row[c * 8 + 2] = f1.x * dv; row[c * 8 + 3] = f1.y * dv;
        row[c * 8 + 4] = f2v.x * dv; row[c * 8 + 5] = f2v.y * dv;
        row[c * 8 + 6] = f3.x * dv; row[c * 8 + 7] = f3.y * dv;
    }

    float logit[CDIM];
    #pragma unroll
    for (int j = 0; j < CDIM; j++) logit[j] = bs[j];
    #pragma unroll
    for (int k = 0; k < HDIM; k++) {
        float v = row[k];
        const float* wr = &w[k * CDIM];
        #pragma unroll
        for (int j = 0; j < CDIM; j++) logit[j] += v * wr[j];
    }

    float mx = logit[0];
    #pragma unroll
    for (int j = 1; j < CDIM; j++) mx = fmaxf(mx, logit[j]);
    float sum = 0.0f;
    #pragma unroll
    for (int j = 0; j < CDIM; j++) sum += __expf(logit[j] - mx);
    float inv = 1.0f / sum;

    float* so = dout + (size_t)i * CDIM;
    #pragma unroll
    for (int j = 0; j < CDIM; j++) so[j] = __expf(logit[j] - mx) * inv;

    if (write_h) {
        float* ho = dout + (size_t)N * CDIM + (size_t)i * CDIM;
        #pragma unroll
        for (int j = 0; j < CDIM; j++) ho[j] = logit[j];
    }
}

// ---------------------------------------------------------------
extern "C" void kernel_launch(void* const* d_in, const int* in_sizes, int n_in,
                              void* d_out, int out_size)
{
    // metadata order: x, edge_index, num_nodes, W1, b1, W2, b2
    const float* x  = (const float*)d_in[0];
    const void*  ei = d_in[1];
    const float* W1 = (const float*)d_in[3];
    const float* b1 = (const float*)d_in[4];
    const float* W2 = (const float*)d_in[5];
    const float* b2 = (const float*)d_in[6];
    float* out = (float*)d_out;

    int N = in_sizes[0] / FDIM;
    int E = in_sizes[1] / 2;
    if (N > NMAX) N = NMAX;
    if (E > EMAX) E = EMAX;
    int write_h = (out_size >= 2 * N * CDIM) ? 1 : 0;

    const int B = 256;

    cudaStream_t s2;
    cudaEvent_t evFork, evJoin, evFork2, evJoin2;
    cudaStreamCreateWithFlags(&s2, cudaStreamNonBlocking);
    cudaEventCreateWithFlags(&evFork, cudaEventDisableTiming);
    cudaEventCreateWithFlags(&evJoin, cudaEventDisableTiming);
    cudaEventCreateWithFlags(&evFork2, cudaEventDisableTiming);
    cudaEventCreateWithFlags(&evJoin2, cudaEventDisableTiming);

    // ---- fork 1: gemm (s2) || edge decode (main) ----
    cudaEventRecord(evFork, 0);
    cudaStreamWaitEvent(s2, evFork, 0);

    k_gemm1raw<<<(N + 31) / 32, 256, 0, s2>>>(x, W1, N);
    cudaEventRecord(evJoin, s2);

    k_init<<<(N + B - 1) / B, B>>>((const int*)ei, N);
    k_convert<<<(E + B - 1) / B, B>>>(ei, E);

    cudaStreamWaitEvent(0, evJoin, 0);
    k_scale<<<(N * 8 + B - 1) / B, B>>>(N);

    // ---- fork 2: chunk-0 pipeline (main) || chunk-1 pipeline (s2) ----
    cudaEventRecord(evFork2, 0);
    cudaStreamWaitEvent(s2, evFork2, 0);

    int propBlocks = (E + B - 1) / B;
    int nodeBlocks = (N + B - 1) / B;

    // stream A (main): chunk 0
    k_prop_c<<<propBlocks, B>>>(E, 0, 0);
    k_mid_c<<<nodeBlocks, B>>>(b1, N, 0);
    k_prop_c<<<propBlocks, B>>>(E, 1, 0);

    // stream B (s2): chunk 1
    k_prop_c<<<propBlocks, B, 0, s2>>>(E, 0, 1);
    k_mid_c<<<nodeBlocks, B, 0, s2>>>(b1, N, 1);
    k_prop_c<<<propBlocks, B, 0, s2>>>(E, 1, 1);
    cudaEventRecord(evJoin2, s2);

    cudaStreamWaitEvent(0, evJoin2, 0);
    k_out<<<(N + B - 1) / B, B>>>(W2, b2, out, N, write_h);

    cudaStreamDestroy(s2);
    cudaEventDestroy(evFork);
    cudaEventDestroy(evJoin);
    cudaEventDestroy(evFork2);
    cudaEventDestroy(evJoin2);
}

// round 14
// speedup vs baseline: 1.1191x; 1.1191x over previous
#include <cuda_runtime.h>
#include <cuda_fp16.h>
#include <cstdint>

// Problem constants: N=100000, F=512, H=16, C=40, E=3200000
#define NMAX 100000
#define EMAX 3200000
#define FDIM 512
#define HDIM 16
#define CDIM 40

// ---- scratch (static device globals; no allocation allowed) ----
__device__ int    g_is64;
__device__ int2   g_edge[EMAX];      // (src, dst)
__device__ int    g_deg[NMAX];
__device__ float2 g_hraw[NMAX * 8];  // fp32 raw x@W1 (pre-scale)
__device__ uint4  g_h   [NMAX * 2];  // fp16 scaled hidden L1 (gather table)
__device__ uint4  g_h2  [NMAX * 2];  // fp16 scaled hidden L2 (gather table)
__device__ uint4  g_agg1[NMAX * 2];  // fp16 accumulator L1 (init = 0)
__device__ uint4  g_agg2[NMAX * 2];  // fp16 accumulator L2 (init = 0)

// ---- f32x2 packed-math helpers (sm_103a) ----
__device__ __forceinline__ unsigned long long f2_fma(
    unsigned long long a, unsigned long long b, unsigned long long c) {
    unsigned long long d;
    asm("fma.rn.f32x2 %0, %1, %2, %3;" : "=l"(d) : "l"(a), "l"(b), "l"(c));
    return d;
}
__device__ __forceinline__ unsigned long long f2_add(
    unsigned long long a, unsigned long long b) {
    unsigned long long d;
    asm("add.rn.f32x2 %0, %1, %2;" : "=l"(d) : "l"(a), "l"(b));
    return d;
}
__device__ __forceinline__ unsigned long long f2_pack(float lo, float hi) {
    unsigned long long d;
    asm("mov.b64 %0, {%1, %2};" : "=l"(d) : "f"(lo), "f"(hi));
    return d;
}

// ---------------------------------------------------------------
// Fork branch A opener: zero degree AND both fp16 accumulators
// (zero-init is hidden under the concurrent 76us GEMM). Thread 0
// detects int64 vs int32 edge buffer.
__global__ void k_init(const int* __restrict__ ei, int N) {
    int i = blockIdx.x * blockDim.x + threadIdx.x;
    if (i < N) {
        g_deg[i] = 0;
        uint4 z = make_uint4(0u, 0u, 0u, 0u);
        g_agg1[i * 2 + 0] = z;
        g_agg1[i * 2 + 1] = z;
        g_agg2[i * 2 + 0] = z;
        g_agg2[i * 2 + 1] = z;
    }
    if (i == 0) {
        int any = 0;
        #pragma unroll
        for (int q = 1; q < 256; q += 2) any |= ei[q];
        g_is64 = (any == 0) ? 1 : 0;
    }
}

// Normalize edges to packed int2 and count in-degree (dst side).
__global__ __launch_bounds__(256) void k_convert(const void* __restrict__ ei, int E) {
    int e = blockIdx.x * blockDim.x + threadIdx.x;
    if (e >= E) return;
    int s, d;
    if (g_is64) {
        const long long* p = (const long long*)ei;
        s = (int)p[e];
        d = (int)p[(long long)E + e];
    } else {
        const int* p = (const int*)ei;
        s = p[e];
        d = p[E + e];
    }
    g_edge[e] = make_int2(s, d);
    atomicAdd(&g_deg[d], 1);
}

// ---------------------------------------------------------------
// GEMM1 (raw): g_hraw[i,:] = x[i,:] @ W1.
// FROZEN R10 config (proven local optimum): 8 warps/block, 4 rows/warp,
// scalar coalesced x loads, f32x2 accumulators, W1 in shared as float2
// j-pairs with odd pitch, value-halving butterfly tail into a separate
// register array, launch_bounds(256,2).
#define WPITCH 513
__global__ __launch_bounds__(256, 2) void k_gemm1raw(
    const float* __restrict__ x, const float* __restrict__ W1, int N)
{
    __shared__ unsigned long long wS[8 * WPITCH];
    {
        const unsigned long long* gw = (const unsigned long long*)W1;
        for (int idx = threadIdx.x; idx < FDIM * 8; idx += 256) {
            int k = idx >> 3, j2 = idx & 7;
            wS[j2 * WPITCH + k] = gw[idx];
        }
    }
    __syncthreads();

    int warp = threadIdx.x >> 5;
    int lane = threadIdx.x & 31;
    int r0 = blockIdx.x * 32 + warp * 4;

    unsigned long long acc[4][8];
    #pragma unroll
    for (int r = 0; r < 4; r++)
        #pragma unroll
        for (int j = 0; j < 8; j++) acc[r][j] = 0ull;

    bool v0 = (r0 + 0) < N, v1 = (r0 + 1) < N, v2 = (r0 + 2) < N, v3 = (r0 + 3) < N;
    const float* x0p = x + (size_t)(r0 + 0) * FDIM + lane;
    const float* x1p = x + (size_t)(r0 + 1) * FDIM + lane;
    const float* x2p = x + (size_t)(r0 + 2) * FDIM + lane;
    const float* x3p = x + (size_t)(r0 + 3) * FDIM + lane;

    #pragma unroll 4
    for (int i = 0; i < 16; i++) {
        int k = lane + 32 * i;
        float x0 = v0 ? x0p[32 * i] : 0.0f;
        float x1 = v1 ? x1p[32 * i] : 0.0f;
        float x2 = v2 ? x2p[32 * i] : 0.0f;
        float x3 = v3 ? x3p[32 * i] : 0.0f;
        unsigned long long p0 = f2_pack(x0, x0);
        unsigned long long p1 = f2_pack(x1, x1);
        unsigned long long p2 = f2_pack(x2, x2);
        unsigned long long p3 = f2_pack(x3, x3);
        #pragma unroll
        for (int j = 0; j < 8; j++) {
            unsigned long long wv = wS[j * WPITCH + k];
            acc[0][j] = f2_fma(p0, wv, acc[0][j]);
            acc[1][j] = f2_fma(p1, wv, acc[1][j]);
            acc[2][j] = f2_fma(p2, wv, acc[2][j]);
            acc[3][j] = f2_fma(p3, wv, acc[3][j]);
        }
    }

    unsigned long long v[32];
    #pragma unroll
    for (int r = 0; r < 4; r++)
        #pragma unroll
        for (int j = 0; j < 8; j++) v[r * 8 + j] = acc[r][j];

    #pragma unroll
    for (int s = 0; s < 5; s++) {
        const int m = 1 << s;
        const int half = 16 >> s;
        bool up = (lane & m) != 0;
        #pragma unroll
        for (int q = 0; q < 16; q++) {
            if (q < half) {
                unsigned long long keep = up ? v[q + half] : v[q];
                unsigned long long mine = up ? v[q] : v[q + half];
                unsigned long long got = __shfl_xor_sync(0xffffffffu, mine, m);
                v[q] = f2_add(keep, got);
            }
        }
    }

    int p = ((lane & 1) << 4) | ((lane & 2) << 2) | (lane & 4) |
            ((lane & 8) >> 2) | ((lane & 16) >> 4);
    int r = p >> 3, j2 = p & 7;
    int row = r0 + r;
    if (row < N) {
        ((unsigned long long*)g_hraw)[(size_t)row * 8 + j2] = v[0];
    }
}

// ---------------------------------------------------------------
// Scale epilogue (after join): g_h = fp16(dinv * hraw). Accumulators
// are pre-zeroed; self-loop is added at the consumer in fp32.
__global__ void k_scale(int N) {
    int idx = blockIdx.x * blockDim.x + threadIdx.x;   // half2 index
    if (idx >= N * 8) return;
    int i = idx >> 3;
    float dv = rsqrtf((float)(g_deg[i] + 1));
    float2 rf = g_hraw[idx];
    rf.x *= dv; rf.y *= dv;
    ((__half2*)g_h)[idx] = __float22half2_rn(rf);
}

// ---------------------------------------------------------------
// Edge propagation: 2 threads per edge, one 16B chunk (8 halves) each.
// (FROZEN R10 shape.)
__global__ __launch_bounds__(256) void k_prop(int E, int layer) {
    int t = blockIdx.x * blockDim.x + threadIdx.x;
    int e = t >> 1;
    if (e >= E) return;
    int c = t & 1;
    const uint4* hin = layer ? g_h2 : g_h;
    uint4* out = layer ? g_agg2 : g_agg1;

    int2 sd = g_edge[e];
    uint4 v = hin[(size_t)sd.x * 2 + c];
    uint4* p = out + (size_t)sd.y * 2 + c;
    asm volatile("red.global.add.noftz.v4.f16x2 [%0], {%1, %2, %3, %4};"
                 :: "l"(p), "r"(v.x), "r"(v.y), "r"(v.z), "r"(v.w)
                 : "memory");
}

// ---------------------------------------------------------------
// Mid layer, per 16B chunk: sum = agg1 + h_self (fp32 add of the
// self-loop term); h2 = fp16(dinv * relu(dinv*sum + b1)).
__global__ void k_mid(const float* __restrict__ b1, int N) {
    int idx = blockIdx.x * blockDim.x + threadIdx.x;   // chunk index
    if (idx >= N * 2) return;
    int i = idx >> 1;
    int c = idx & 1;
    float dv = rsqrtf((float)(g_deg[i] + 1));
    uint4 a = g_agg1[idx];
    uint4 s = g_h[idx];
    float2 f0 = __half22float2(*(__half2*)&a.x);
    float2 f1 = __half22float2(*(__half2*)&a.y);
    float2 f2v = __half22float2(*(__half2*)&a.z);
    float2 f3 = __half22float2(*(__half2*)&a.w);
    float2 s0 = __half22float2(*(__half2*)&s.x);
    float2 s1 = __half22float2(*(__half2*)&s.y);
    float2 s2 = __half22float2(*(__half2*)&s.z);
    float2 s3 = __half22float2(*(__half2*)&s.w);
    f0.x += s0.x; f0.y += s0.y; f1.x += s1.x; f1.y += s1.y;
    f2v.x += s2.x; f2v.y += s2.y; f3.x += s3.x; f3.y += s3.y;
    const float4* b4 = (const float4*)b1;
    float4 bb0 = b4[c * 2 + 0];
    float4 bb1 = b4[c * 2 + 1];
    float2 r0, r1, r2, r3;
    r0.x = fmaxf(dv * f0.x + bb0.x, 0.f) * dv;
    r0.y = fmaxf(dv * f0.y + bb0.y, 0.f) * dv;
    r1.x = fmaxf(dv * f1.x + bb0.z, 0.f) * dv;
    r1.y = fmaxf(dv * f1.y + bb0.w, 0.f) * dv;
    r2.x = fmaxf(dv * f2v.x + bb1.x, 0.f) * dv;
    r2.y = fmaxf(dv * f2v.y + bb1.y, 0.f) * dv;
    r3.x = fmaxf(dv * f3.x + bb1.z, 0.f) * dv;
    r3.y = fmaxf(dv * f3.y + bb1.w, 0.f) * dv;
    uint4 o;
    *(__half2*)&o.x = __float22half2_rn(r0);
    *(__half2*)&o.y = __float22half2_rn(r1);
    *(__half2*)&o.z = __float22half2_rn(r2);
    *(__half2*)&o.w = __float22half2_rn(r3);
    g_h2[idx] = o;
}

// ---------------------------------------------------------------
// Output: row = dinv*(agg2 + h2_self); logits = row@W2 + b2; softmax.
// d_out[0:N*40) = softmax ; d_out[N*40:2N*40) = logits
__global__ __launch_bounds__(256) void k_out(
    const float* __restrict__ W2, const float* __restrict__ b2,
    float* __restrict__ dout, int N, int write_h)
{
    __shared__ float w[HDIM * CDIM];
    __shared__ float bs[CDIM];
    for (int i = threadIdx.x; i < HDIM * CDIM; i += blockDim.x) w[i] = W2[i];
    if (threadIdx.x < CDIM) bs[threadIdx.x] = b2[threadIdx.x];
    __syncthreads();

    int i = blockIdx.x * blockDim.x + threadIdx.x;
    if (i >= N) return;

    float dv = rsqrtf((float)(g_deg[i] + 1));
    float row[HDIM];
    #pragma unroll
    for (int c = 0; c < 2; c++) {
        uint4 a = g_agg2[(size_t)i * 2 + c];
        uint4 s = g_h2[(size_t)i * 2 + c];
        float2 f0 = __half22float2(*(__half2*)&a.x);
        float2 f1 = __half22float2(*(__half2*)&a.y);
        float2 f2v = __half22float2(*(__half2*)&a.z);
        float2 f3 = __half22float2(*(__half2*)&a.w);
        float2 s0 = __half22float2(*(__half2*)&s.x);
        float2 s1 = __half22float2(*(__half2*)&s.y);
        float2 s2 = __half22float2(*(__half2*)&s.z);
        float2 s3 = __half22float2(*(__half2*)&s.w);
        row[c * 8 + 0] = (f0.x + s0.x) * dv; row[c * 8 + 1] = (f0.y + s0.y) * dv;
        row[c * 8 + 2] = (f1.x + s1.x) * dv; row[c * 8 + 3] = (f1.y + s1.y) * dv;
        row[c * 8 + 4] = (f2v.x + s2.x) * dv; row[c * 8 + 5] = (f2v.y + s2.y) * dv;
        row[c * 8 + 6] = (f3.x + s3.x) * dv; row[c * 8 + 7] = (f3.y + s3.y) * dv;
    }

    float logit[CDIM];
    #pragma unroll
    for (int j = 0; j < CDIM; j++) logit[j] = bs[j];
    #pragma unroll
    for (int k = 0; k < HDIM; k++) {
        float v = row[k];
        const float* wr = &w[k * CDIM];
        #pragma unroll
        for (int j = 0; j < CDIM; j++) logit[j] += v * wr[j];
    }

    float mx = logit[0];
    #pragma unroll
    for (int j = 1; j < CDIM; j++) mx = fmaxf(mx, logit[j]);
    float sum = 0.0f;
    #pragma unroll
    for (int j = 0; j < CDIM; j++) sum += __expf(logit[j] - mx);
    float inv = 1.0f / sum;

    float* so = dout + (size_t)i * CDIM;
    #pragma unroll
    for (int j = 0; j < CDIM; j++) so[j] = __expf(logit[j] - mx) * inv;

    if (write_h) {
        float* ho = dout + (size_t)N * CDIM + (size_t)i * CDIM;
        #pragma unroll
        for (int j = 0; j < CDIM; j++) ho[j] = logit[j];
    }
}

// ---------------------------------------------------------------
extern "C" void kernel_launch(void* const* d_in, const int* in_sizes, int n_in,
                              void* d_out, int out_size)
{
    // metadata order: x, edge_index, num_nodes, W1, b1, W2, b2
    const float* x  = (const float*)d_in[0];
    const void*  ei = d_in[1];
    const float* W1 = (const float*)d_in[3];
    const float* b1 = (const float*)d_in[4];
    const float* W2 = (const float*)d_in[5];
    const float* b2 = (const float*)d_in[6];
    float* out = (float*)d_out;

    int N = in_sizes[0] / FDIM;
    int E = in_sizes[1] / 2;
    if (N > NMAX) N = NMAX;
    if (E > EMAX) E = EMAX;
    int write_h = (out_size >= 2 * N * CDIM) ? 1 : 0;

    const int B = 256;

    // Fork-join: edge processing + accumulator zeroing (L2-bound) run
    // concurrently with the raw GEMM (SM-bound) on a second stream.
    cudaStream_t s2;
    cudaEvent_t evFork, evJoin;
    cudaStreamCreateWithFlags(&s2, cudaStreamNonBlocking);
    cudaEventCreateWithFlags(&evFork, cudaEventDisableTiming);
    cudaEventCreateWithFlags(&evJoin, cudaEventDisableTiming);

    cudaEventRecord(evFork, 0);
    cudaStreamWaitEvent(s2, evFork, 0);

    // branch B (s2): raw GEMM, independent of edges
    k_gemm1raw<<<(N + 31) / 32, 256, 0, s2>>>(x, W1, N);
    cudaEventRecord(evJoin, s2);

    // branch A (main stream): zero + edge decode + degree
    k_init<<<(N + B - 1) / B, B>>>((const int*)ei, N);
    k_convert<<<(E + B - 1) / B, B>>>(ei, E);

    // join
    cudaStreamWaitEvent(0, evJoin, 0);

    k_scale<<<(N * 8 + B - 1) / B, B>>>(N);

    k_prop<<<((size_t)E * 2 + B - 1) / B, B>>>(E, 0);
    k_mid<<<(N * 2 + B - 1) / B, B>>>(b1, N);
    k_prop<<<((size_t)E * 2 + B - 1) / B, B>>>(E, 1);

    k_out<<<(N + B - 1) / B, B>>>(W2, b2, out, N, write_h);

    cudaStreamDestroy(s2);
    cudaEventDestroy(evFork);
    cudaEventDestroy(evJoin);
}

// round 15
// speedup vs baseline: 1.2273x; 1.0966x over previous
#include <cuda_runtime.h>
#include <cuda_fp16.h>
#include <cstdint>
#include <cstring>

// Problem constants: N=100000, F=512, H=16, C=40, E=3200000
#define NMAX 100000
#define EMAX 3200000
#define FDIM 512
#define HDIM 16
#define CDIM 40

// ---- scratch (static device globals; no allocation allowed) ----
__device__ int    g_is64;
__device__ int2   g_edge[EMAX];      // (src, dst)
__device__ int    g_deg[NMAX];
__device__ float2 g_hraw[NMAX * 8];  // fp32 raw x@W1 (pre-scale)
__device__ uint4  g_h   [NMAX * 2];  // fp16 scaled hidden L1 (gather table)
__device__ uint4  g_h2  [NMAX * 2];  // fp16 scaled hidden L2 (gather table)
__device__ uint4  g_agg1[NMAX * 2];  // fp16 accumulator L1 (init = g_h row)
__device__ uint4  g_agg2[NMAX * 2];  // fp16 accumulator L2 (init = g_h2 row)

// ---------------------------------------------------------------
__global__ void k_init(const int* __restrict__ ei, int N) {
    int i = blockIdx.x * blockDim.x + threadIdx.x;
    if (i < N) g_deg[i] = 0;
    if (i == 0) {
        int any = 0;
        #pragma unroll
        for (int q = 1; q < 256; q += 2) any |= ei[q];
        g_is64 = (any == 0) ? 1 : 0;
    }
}

// Normalize edges to packed int2 and count in-degree (dst side).
__global__ __launch_bounds__(256) void k_convert(const void* __restrict__ ei, int E) {
    int e = blockIdx.x * blockDim.x + threadIdx.x;
    if (e >= E) return;
    int s, d;
    if (g_is64) {
        const long long* p = (const long long*)ei;
        s = (int)p[e];
        d = (int)p[(long long)E + e];
    } else {
        const int* p = (const int*)ei;
        s = p[e];
        d = p[E + e];
    }
    g_edge[e] = make_int2(s, d);
    atomicAdd(&g_deg[d], 1);
}

// ---------------------------------------------------------------
// Tensor-core GEMM1 (raw): g_hraw[i,:] = x[i,:] @ W1, fp32-accurate
// via fp16 hi/lo splitting: x = xh + xl, W = Wh + Wl;
//   D = xh@Wh + xh@Wl + xl@Wh   (xl@Wl ~ 2.4e-7 rel, dropped)
// mma.sync.aligned.m16n8k16.row.col.f32.f16.f16.f32.
// One warp computes 16 rows x 16 cols; 2 n-tiles of 8; 32 k-steps.
// W staged in shared n-major (Wt[n][k], pitch 520 halves -> the
// warp's 32 LDS.32 addresses hit all 32 banks exactly once).
// Fragment layout (g = lane>>2, tc = lane&3):
//   A: a0={A[g][c],A[g][c+1]}, a1={A[g+8][c],...}, a2={A[g][c+8],...},
//      a3={A[g+8][c+8],...},  c = 16*ks + 2*tc
//   B: b0={B[c][n],B[c+1][n]}, b1={B[c+8][n],B[c+9][n]}, n = g (+8 per tile)
//   D: d0=D[g][2tc], d1=D[g][2tc+1], d2=D[g+8][2tc], d3=D[g+8][2tc+1]
#define WT_PITCH 520
#define MMA16816(d, a0, a1, a2, a3, b0, b1) \
    asm volatile("mma.sync.aligned.m16n8k16.row.col.f32.f16.f16.f32 " \
        "{%0,%1,%2,%3}, {%4,%5,%6,%7}, {%8,%9}, {%0,%1,%2,%3};" \
        : "+f"((d)[0]), "+f"((d)[1]), "+f"((d)[2]), "+f"((d)[3]) \
        : "r"(a0), "r"(a1), "r"(a2), "r"(a3), "r"(b0), "r"(b1))

__device__ __forceinline__ uint32_t h2u(__half2 h) {
    uint32_t u; memcpy(&u, &h, 4); return u;
}

__global__ __launch_bounds__(256) void k_gemm_mma(
    const float* __restrict__ x, const float* __restrict__ W1, int N)
{
    __shared__ __half sWh[16 * WT_PITCH];
    __shared__ __half sWl[16 * WT_PITCH];
    // W1 is [512][16] row-major (k-major rows). Store transposed: Wt[n][k].
    for (int idx = threadIdx.x; idx < FDIM * HDIM; idx += 256) {
        int k = idx >> 4, n = idx & 15;
        float w = W1[idx];
        __half wh = __float2half_rn(w);
        sWh[n * WT_PITCH + k] = wh;
        sWl[n * WT_PITCH + k] = __float2half_rn(w - __half2float(wh));
    }
    __syncthreads();

    int warp = threadIdx.x >> 5;
    int lane = threadIdx.x & 31;
    int g = lane >> 2;
    int tc = lane & 3;
    int rowBase = blockIdx.x * 128 + warp * 16;
    if (rowBase >= N) return;    // N % 16 == 0: warps are all-or-nothing

    const float* xp0 = x + (size_t)(rowBase + g) * FDIM;
    const float* xp8 = x + (size_t)(rowBase + g + 8) * FDIM;

    float d0[4] = {0.f, 0.f, 0.f, 0.f};
    float d1[4] = {0.f, 0.f, 0.f, 0.f};

    #pragma unroll 2
    for (int ks = 0; ks < 32; ks++) {
        int c = ks * 16 + tc * 2;
        float2 p00 = *(const float2*)(xp0 + c);       // A[g][c..c+1]
        float2 p80 = *(const float2*)(xp8 + c);       // A[g+8][c..c+1]
        float2 p01 = *(const float2*)(xp0 + c + 8);   // A[g][c+8..c+9]
        float2 p81 = *(const float2*)(xp8 + c + 8);   // A[g+8][c+8..c+9]

        __half2 h00 = __floats2half2_rn(p00.x, p00.y);
        __half2 h80 = __floats2half2_rn(p80.x, p80.y);
        __half2 h01 = __floats2half2_rn(p01.x, p01.y);
        __half2 h81 = __floats2half2_rn(p81.x, p81.y);

        float2 q00 = __half22float2(h00);
        float2 q80 = __half22float2(h80);
        float2 q01 = __half22float2(h01);
        float2 q81 = __half22float2(h81);
        __half2 l00 = __floats2half2_rn(p00.x - q00.x, p00.y - q00.y);
        __half2 l80 = __floats2half2_rn(p80.x - q80.x, p80.y - q80.y);
        __half2 l01 = __floats2half2_rn(p01.x - q01.x, p01.y - q01.y);
        __half2 l81 = __floats2half2_rn(p81.x - q81.x, p81.y - q81.y);

        uint32_t ah0 = h2u(h00), ah1 = h2u(h80), ah2 = h2u(h01), ah3 = h2u(h81);
        uint32_t al0 = h2u(l00), al1 = h2u(l80), al2 = h2u(l01), al3 = h2u(l81);

        #pragma unroll
        for (int j = 0; j < 2; j++) {
            int n = j * 8 + g;
            const __half* bh = &sWh[n * WT_PITCH + c];
            const __half* bl = &sWl[n * WT_PITCH + c];
            uint32_t bh0 = *(const uint32_t*)bh;
            uint32_t bh1 = *(const uint32_t*)(bh + 8);
            uint32_t bl0 = *(const uint32_t*)bl;
            uint32_t bl1 = *(const uint32_t*)(bl + 8);
            float* dd = j ? d1 : d0;
            MMA16816(dd, ah0, ah1, ah2, ah3, bh0, bh1);   // xh @ Wh
            MMA16816(dd, ah0, ah1, ah2, ah3, bl0, bl1);   // xh @ Wl
            MMA16816(dd, al0, al1, al2, al3, bh0, bh1);   // xl @ Wh
        }
    }

    int r0 = rowBase + g, r8 = rowBase + g + 8;
    g_hraw[(size_t)r0 * 8 + 0 + tc] = make_float2(d0[0], d0[1]);
    g_hraw[(size_t)r8 * 8 + 0 + tc] = make_float2(d0[2], d0[3]);
    g_hraw[(size_t)r0 * 8 + 4 + tc] = make_float2(d1[0], d1[1]);
    g_hraw[(size_t)r8 * 8 + 4 + tc] = make_float2(d1[2], d1[3]);
}

// ---------------------------------------------------------------
// Scale epilogue (after join): hs = fp16(dinv * hraw), dinv computed
// inline from deg. Writes gather table g_h and accumulator init g_agg1.
__global__ void k_scale(int N) {
    int idx = blockIdx.x * blockDim.x + threadIdx.x;   // half2 index
    if (idx >= N * 8) return;
    int i = idx >> 3;
    float dv = rsqrtf((float)(g_deg[i] + 1));
    float2 rf = g_hraw[idx];
    rf.x *= dv; rf.y *= dv;
    __half2 hv = __float22half2_rn(rf);
    ((__half2*)g_h)[idx] = hv;
    ((__half2*)g_agg1)[idx] = hv;
}

// ---------------------------------------------------------------
// Edge propagation: 2 threads per edge, one 16B chunk (8 halves) each.
// (FROZEN R10 shape.)
__global__ __launch_bounds__(256) void k_prop(int E, int layer) {
    int t = blockIdx.x * blockDim.x + threadIdx.x;
    int e = t >> 1;
    if (e >= E) return;
    int c = t & 1;
    const uint4* hin = layer ? g_h2 : g_h;
    uint4* out = layer ? g_agg2 : g_agg1;

    int2 sd = g_edge[e];
    uint4 v = hin[(size_t)sd.x * 2 + c];
    uint4* p = out + (size_t)sd.y * 2 + c;
    asm volatile("red.global.add.noftz.v4.f16x2 [%0], {%1, %2, %3, %4};"
                 :: "l"(p), "r"(v.x), "r"(v.y), "r"(v.z), "r"(v.w)
                 : "memory");
}

// ---------------------------------------------------------------
// Mid layer, per 16B chunk: out1 = relu(dinv*agg1 + b1); hs2 = dinv*out1
// writes g_h2 (gather table) and g_agg2 (self-loop init), both fp16.
__global__ void k_mid(const float* __restrict__ b1, int N) {
    int idx = blockIdx.x * blockDim.x + threadIdx.x;   // chunk index
    if (idx >= N * 2) return;
    int i = idx >> 1;
    int c = idx & 1;
    float dv = rsqrtf((float)(g_deg[i] + 1));
    uint4 a = g_agg1[idx];
    float2 f0 = __half22float2(*(__half2*)&a.x);
    float2 f1 = __half22float2(*(__half2*)&a.y);
    float2 f2v = __half22float2(*(__half2*)&a.z);
    float2 f3 = __half22float2(*(__half2*)&a.w);
    const float4* b4 = (const float4*)b1;
    float4 bb0 = b4[c * 2 + 0];
    float4 bb1 = b4[c * 2 + 1];
    float2 r0, r1, r2, r3;
    r0.x = fmaxf(dv * f0.x + bb0.x, 0.f) * dv;
    r0.y = fmaxf(dv * f0.y + bb0.y, 0.f) * dv;
    r1.x = fmaxf(dv * f1.x + bb0.z, 0.f) * dv;
    r1.y = fmaxf(dv * f1.y + bb0.w, 0.f) * dv;
    r2.x = fmaxf(dv * f2v.x + bb1.x, 0.f) * dv;
    r2.y = fmaxf(dv * f2v.y + bb1.y, 0.f) * dv;
    r3.x = fmaxf(dv * f3.x + bb1.z, 0.f) * dv;
    r3.y = fmaxf(dv * f3.y + bb1.w, 0.f) * dv;
    uint4 o;
    *(__half2*)&o.x = __float22half2_rn(r0);
    *(__half2*)&o.y = __float22half2_rn(r1);
    *(__half2*)&o.z = __float22half2_rn(r2);
    *(__half2*)&o.w = __float22half2_rn(r3);
    g_h2[idx] = o;
    g_agg2[idx] = o;
}

// ---------------------------------------------------------------
// Output: logits = (dinv[i]*agg2[i,:]) @ W2 + b2 ; out = softmax
// d_out[0:N*40) = softmax ; d_out[N*40:2N*40) = logits
__global__ __launch_bounds__(256) void k_out(
    const float* __restrict__ W2, const float* __restrict__ b2,
    float* __restrict__ dout, int N, int write_h)
{
    __shared__ float w[HDIM * CDIM];
    __shared__ float bs[CDIM];
    for (int i = threadIdx.x; i < HDIM * CDIM; i += blockDim.x) w[i] = W2[i];
    if (threadIdx.x < CDIM) bs[threadIdx.x] = b2[threadIdx.x];
    __syncthreads();

    int i = blockIdx.x * blockDim.x + threadIdx.x;
    if (i >= N) return;

    float dv = rsqrtf((float)(g_deg[i] + 1));
    float row[HDIM];
    #pragma unroll
    for (int c = 0; c < 2; c++) {
        uint4 a = g_agg2[(size_t)i * 2 + c];
        float2 f0 = __half22float2(*(__half2*)&a.x);
        float2 f1 = __half22float2(*(__half2*)&a.y);
        float2 f2v = __half22float2(*(__half2*)&a.z);
        float2 f3 = __half22float2(*(__half2*)&a.w);
        row[c * 8 + 0] = f0.x * dv; row[c * 8 + 1] = f0.y * dv;
        row[c * 8 + 2] = f1.x * dv; row[c * 8 + 3] = f1.y * dv;
        row[c * 8 + 4] = f2v.x * dv; row[c * 8 + 5] = f2v.y * dv;
        row[c * 8 + 6] = f3.x * dv; row[c * 8 + 7] = f3.y * dv;
    }

    float logit[CDIM];
    #pragma unroll
    for (int j = 0; j < CDIM; j++) logit[j] = bs[j];
    #pragma unroll
    for (int k = 0; k < HDIM; k++) {
        float v = row[k];
        const float* wr = &w[k * CDIM];
        #pragma unroll
        for (int j = 0; j < CDIM; j++) logit[j] += v * wr[j];
    }

    float mx = logit[0];
    #pragma unroll
    for (int j = 1; j < CDIM; j++) mx = fmaxf(mx, logit[j]);
    float sum = 0.0f;
    #pragma unroll
    for (int j = 0; j < CDIM; j++) sum += __expf(logit[j] - mx);
    float inv = 1.0f / sum;

    float* so = dout + (size_t)i * CDIM;
    #pragma unroll
    for (int j = 0; j < CDIM; j++) so[j] = __expf(logit[j] - mx) * inv;

    if (write_h) {
        float* ho = dout + (size_t)N * CDIM + (size_t)i * CDIM;
        #pragma unroll
        for (int j = 0; j < CDIM; j++) ho[j] = logit[j];
    }
}

// ---------------------------------------------------------------
extern "C" void kernel_launch(void* const* d_in, const int* in_sizes, int n_in,
                              void* d_out, int out_size)
{
    // metadata order: x, edge_index, num_nodes, W1, b1, W2, b2
    const float* x  = (const float*)d_in[0];
    const void*  ei = d_in[1];
    const float* W1 = (const float*)d_in[3];
    const float* b1 = (const float*)d_in[4];
    const float* W2 = (const float*)d_in[5];
    const float* b2 = (const float*)d_in[6];
    float* out = (float*)d_out;

    int N = in_sizes[0] / FDIM;
    int E = in_sizes[1] / 2;
    if (N > NMAX) N = NMAX;
    if (E > EMAX) E = EMAX;
    int write_h = (out_size >= 2 * N * CDIM) ? 1 : 0;

    const int B = 256;

    // Fork-join: edge processing (L2/atomic-bound) runs concurrently
    // with the tensor-core GEMM (DRAM-bound) on a second stream.
    cudaStream_t s2;
    cudaEvent_t evFork, evJoin;
    cudaStreamCreateWithFlags(&s2, cudaStreamNonBlocking);
    cudaEventCreateWithFlags(&evFork, cudaEventDisableTiming);
    cudaEventCreateWithFlags(&evJoin, cudaEventDisableTiming);

    cudaEventRecord(evFork, 0);
    cudaStreamWaitEvent(s2, evFork, 0);

    // branch B (s2): raw GEMM via HMMA, independent of edges
    k_gemm_mma<<<(N + 127) / 128, 256, 0, s2>>>(x, W1, N);
    cudaEventRecord(evJoin, s2);

    // branch A (main stream): edge decode + degree
    k_init<<<(N + B - 1) / B, B>>>((const int*)ei, N);
    k_convert<<<(E + B - 1) / B, B>>>(ei, E);

    // join
    cudaStreamWaitEvent(0, evJoin, 0);

    k_scale<<<(N * 8 + B - 1) / B, B>>>(N);

    k_prop<<<((size_t)E * 2 + B - 1) / B, B>>>(E, 0);
    k_mid<<<(N * 2 + B - 1) / B, B>>>(b1, N);
    k_prop<<<((size_t)E * 2 + B - 1) / B, B>>>(E, 1);

    k_out<<<(N + B - 1) / B, B>>>(W2, b2, out, N, write_h);

    cudaStreamDestroy(s2);
    cudaEventDestroy(evFork);
    cudaEventDestroy(evJoin);
}

// round 16
// speedup vs baseline: 1.2420x; 1.0120x over previous
#include <cuda_runtime.h>
#include <cuda_fp16.h>
#include <cstdint>
#include <cstring>

// Problem constants: N=100000, F=512, H=16, C=40, E=3200000
#define NMAX 100000
#define EMAX 3200000
#define FDIM 512
#define HDIM 16
#define CDIM 40

// ---- scratch (static device globals; no allocation allowed) ----
__device__ int    g_is64;
__device__ int2   g_edge[EMAX];      // (src, dst)
__device__ int    g_deg[NMAX];
__device__ float2 g_hraw[NMAX * 8];  // fp32 raw x@W1 (pre-scale)
__device__ uint4  g_h   [NMAX * 2];  // fp16 scaled hidden L1 (gather table)
__device__ uint4  g_h2  [NMAX * 2];  // fp16 scaled hidden L2 (gather table)
__device__ uint4  g_agg1[NMAX * 2];  // fp16 accumulator L1 (init = g_h row)
__device__ uint4  g_agg2[NMAX * 2];  // fp16 accumulator L2 (init = g_h2 row)

// ---------------------------------------------------------------
__global__ void k_init(const int* __restrict__ ei, int N) {
    int i = blockIdx.x * blockDim.x + threadIdx.x;
    if (i < N) g_deg[i] = 0;
    if (i == 0) {
        int any = 0;
        #pragma unroll
        for (int q = 1; q < 256; q += 2) any |= ei[q];
        g_is64 = (any == 0) ? 1 : 0;
    }
}

// Normalize edges to packed int2 and count in-degree (dst side).
__global__ __launch_bounds__(256) void k_convert(const void* __restrict__ ei, int E) {
    int e = blockIdx.x * blockDim.x + threadIdx.x;
    if (e >= E) return;
    int s, d;
    if (g_is64) {
        const long long* p = (const long long*)ei;
        s = (int)p[e];
        d = (int)p[(long long)E + e];
    } else {
        const int* p = (const int*)ei;
        s = p[e];
        d = p[E + e];
    }
    g_edge[e] = make_int2(s, d);
    atomicAdd(&g_deg[d], 1);
}

// ---------------------------------------------------------------
// Tensor-core GEMM1 (raw): g_hraw[i,:] = x[i,:] @ W1, fp32-accurate
// via fp16 hi/lo splitting (D = xh@Wh + xh@Wl + xl@Wh), with a
// DEPTH-2 SOFTWARE PIPELINE on the x loads: loads for step ks+2 are
// issued before the convert+MMA work of step ks, keeping 8 LDG.64
// in flight per thread to cover DRAM latency.
// Fragment layout identical to R15 (verified correct).
#define WT_PITCH 520
#define MMA16816(d, a0, a1, a2, a3, b0, b1) \
    asm volatile("mma.sync.aligned.m16n8k16.row.col.f32.f16.f16.f32 " \
        "{%0,%1,%2,%3}, {%4,%5,%6,%7}, {%8,%9}, {%0,%1,%2,%3};" \
        : "+f"((d)[0]), "+f"((d)[1]), "+f"((d)[2]), "+f"((d)[3]) \
        : "r"(a0), "r"(a1), "r"(a2), "r"(a3), "r"(b0), "r"(b1))

__device__ __forceinline__ uint32_t h2u(__half2 h) {
    uint32_t u; memcpy(&u, &h, 4); return u;
}

__global__ __launch_bounds__(256) void k_gemm_mma(
    const float* __restrict__ x, const float* __restrict__ W1, int N)
{
    __shared__ __half sWh[16 * WT_PITCH];
    __shared__ __half sWl[16 * WT_PITCH];
    // W1 is [512][16] row-major. Store transposed: Wt[n][k].
    for (int idx = threadIdx.x; idx < FDIM * HDIM; idx += 256) {
        int k = idx >> 4, n = idx & 15;
        float w = W1[idx];
        __half wh = __float2half_rn(w);
        sWh[n * WT_PITCH + k] = wh;
        sWl[n * WT_PITCH + k] = __float2half_rn(w - __half2float(wh));
    }
    __syncthreads();

    int warp = threadIdx.x >> 5;
    int lane = threadIdx.x & 31;
    int g = lane >> 2;
    int tc = lane & 3;
    int rowBase = blockIdx.x * 128 + warp * 16;
    if (rowBase >= N) return;    // N % 16 == 0: warps all-or-nothing

    const float* xp0 = x + (size_t)(rowBase + g) * FDIM;
    const float* xp8 = x + (size_t)(rowBase + g + 8) * FDIM;

    float d0[4] = {0.f, 0.f, 0.f, 0.f};
    float d1[4] = {0.f, 0.f, 0.f, 0.f};

    // depth-2 prefetch buffer: buf[parity][0..3]
    float2 buf[2][4];
    #pragma unroll
    for (int p = 0; p < 2; p++) {
        int c = p * 16 + tc * 2;
        buf[p][0] = *(const float2*)(xp0 + c);
        buf[p][1] = *(const float2*)(xp8 + c);
        buf[p][2] = *(const float2*)(xp0 + c + 8);
        buf[p][3] = *(const float2*)(xp8 + c + 8);
    }

    #pragma unroll 4
    for (int ks = 0; ks < 32; ks++) {
        int par = ks & 1;
        float2 p00 = buf[par][0];
        float2 p80 = buf[par][1];
        float2 p01 = buf[par][2];
        float2 p81 = buf[par][3];

        // issue loads for step ks+2 before any convert/MMA work
        if (ks + 2 < 32) {
            int cn = (ks + 2) * 16 + tc * 2;
            buf[par][0] = *(const float2*)(xp0 + cn);
            buf[par][1] = *(const float2*)(xp8 + cn);
            buf[par][2] = *(const float2*)(xp0 + cn + 8);
            buf[par][3] = *(const float2*)(xp8 + cn + 8);
        }

        int c = ks * 16 + tc * 2;

        __half2 h00 = __floats2half2_rn(p00.x, p00.y);
        __half2 h80 = __floats2half2_rn(p80.x, p80.y);
        __half2 h01 = __floats2half2_rn(p01.x, p01.y);
        __half2 h81 = __floats2half2_rn(p81.x, p81.y);

        float2 q00 = __half22float2(h00);
        float2 q80 = __half22float2(h80);
        float2 q01 = __half22float2(h01);
        float2 q81 = __half22float2(h81);
        __half2 l00 = __floats2half2_rn(p00.x - q00.x, p00.y - q00.y);
        __half2 l80 = __floats2half2_rn(p80.x - q80.x, p80.y - q80.y);
        __half2 l01 = __floats2half2_rn(p01.x - q01.x, p01.y - q01.y);
        __half2 l81 = __floats2half2_rn(p81.x - q81.x, p81.y - q81.y);

        uint32_t ah0 = h2u(h00), ah1 = h2u(h80), ah2 = h2u(h01), ah3 = h2u(h81);
        uint32_t al0 = h2u(l00), al1 = h2u(l80), al2 = h2u(l01), al3 = h2u(l81);

        #pragma unroll
        for (int j = 0; j < 2; j++) {
            int n = j * 8 + g;
            const __half* bh = &sWh[n * WT_PITCH + c];
            const __half* bl = &sWl[n * WT_PITCH + c];
            uint32_t bh0 = *(const uint32_t*)bh;
            uint32_t bh1 = *(const uint32_t*)(bh + 8);
            uint32_t bl0 = *(const uint32_t*)bl;
            uint32_t bl1 = *(const uint32_t*)(bl + 8);
            float* dd = j ? d1 : d0;
            MMA16816(dd, ah0, ah1, ah2, ah3, bh0, bh1);   // xh @ Wh
            MMA16816(dd, ah0, ah1, ah2, ah3, bl0, bl1);   // xh @ Wl
            MMA16816(dd, al0, al1, al2, al3, bh0, bh1);   // xl @ Wh
        }
    }

    int r0 = rowBase + g, r8 = rowBase + g + 8;
    g_hraw[(size_t)r0 * 8 + 0 + tc] = make_float2(d0[0], d0[1]);
    g_hraw[(size_t)r8 * 8 + 0 + tc] = make_float2(d0[2], d0[3]);
    g_hraw[(size_t)r0 * 8 + 4 + tc] = make_float2(d1[0], d1[1]);
    g_hraw[(size_t)r8 * 8 + 4 + tc] = make_float2(d1[2], d1[3]);
}

// ---------------------------------------------------------------
// Scale epilogue (after join): hs = fp16(dinv * hraw), dinv computed
// inline from deg. Writes gather table g_h and accumulator init g_agg1.
__global__ void k_scale(int N) {
    int idx = blockIdx.x * blockDim.x + threadIdx.x;   // half2 index
    if (idx >= N * 8) return;
    int i = idx >> 3;
    float dv = rsqrtf((float)(g_deg[i] + 1));
    float2 rf = g_hraw[idx];
    rf.x *= dv; rf.y *= dv;
    __half2 hv = __float22half2_rn(rf);
    ((__half2*)g_h)[idx] = hv;
    ((__half2*)g_agg1)[idx] = hv;
}

// ---------------------------------------------------------------
// Edge propagation: 2 threads per edge, one 16B chunk (8 halves) each.
// (FROZEN R10 shape.)
__global__ __launch_bounds__(256) void k_prop(int E, int layer) {
    int t = blockIdx.x * blockDim.x + threadIdx.x;
    int e = t >> 1;
    if (e >= E) return;
    int c = t & 1;
    const uint4* hin = layer ? g_h2 : g_h;
    uint4* out = layer ? g_agg2 : g_agg1;

    int2 sd = g_edge[e];
    uint4 v = hin[(size_t)sd.x * 2 + c];
    uint4* p = out + (size_t)sd.y * 2 + c;
    asm volatile("red.global.add.noftz.v4.f16x2 [%0], {%1, %2, %3, %4};"
                 :: "l"(p), "r"(v.x), "r"(v.y), "r"(v.z), "r"(v.w)
                 : "memory");
}

// ---------------------------------------------------------------
// Mid layer, per 16B chunk: out1 = relu(dinv*agg1 + b1); hs2 = dinv*out1
// writes g_h2 (gather table) and g_agg2 (self-loop init), both fp16.
__global__ void k_mid(const float* __restrict__ b1, int N) {
    int idx = blockIdx.x * blockDim.x + threadIdx.x;   // chunk index
    if (idx >= N * 2) return;
    int i = idx >> 1;
    int c = idx & 1;
    float dv = rsqrtf((float)(g_deg[i] + 1));
    uint4 a = g_agg1[idx];
    float2 f0 = __half22float2(*(__half2*)&a.x);
    float2 f1 = __half22float2(*(__half2*)&a.y);
    float2 f2v = __half22float2(*(__half2*)&a.z);
    float2 f3 = __half22float2(*(__half2*)&a.w);
    const float4* b4 = (const float4*)b1;
    float4 bb0 = b4[c * 2 + 0];
    float4 bb1 = b4[c * 2 + 1];
    float2 r0, r1, r2, r3;
    r0.x = fmaxf(dv * f0.x + bb0.x, 0.f) * dv;
    r0.y = fmaxf(dv * f0.y + bb0.y, 0.f) * dv;
    r1.x = fmaxf(dv * f1.x + bb0.z, 0.f) * dv;
    r1.y = fmaxf(dv * f1.y + bb0.w, 0.f) * dv;
    r2.x = fmaxf(dv * f2v.x + bb1.x, 0.f) * dv;
    r2.y = fmaxf(dv * f2v.y + bb1.y, 0.f) * dv;
    r3.x = fmaxf(dv * f3.x + bb1.z, 0.f) * dv;
    r3.y = fmaxf(dv * f3.y + bb1.w, 0.f) * dv;
    uint4 o;
    *(__half2*)&o.x = __float22half2_rn(r0);
    *(__half2*)&o.y = __float22half2_rn(r1);
    *(__half2*)&o.z = __float22half2_rn(r2);
    *(__half2*)&o.w = __float22half2_rn(r3);
    g_h2[idx] = o;
    g_agg2[idx] = o;
}

// ---------------------------------------------------------------
// Output: logits = (dinv[i]*agg2[i,:]) @ W2 + b2 ; out = softmax
// d_out[0:N*40) = softmax ; d_out[N*40:2N*40) = logits
__global__ __launch_bounds__(256) void k_out(
    const float* __restrict__ W2, const float* __restrict__ b2,
    float* __restrict__ dout, int N, int write_h)
{
    __shared__ float w[HDIM * CDIM];
    __shared__ float bs[CDIM];
    for (int i = threadIdx.x; i < HDIM * CDIM; i += blockDim.x) w[i] = W2[i];
    if (threadIdx.x < CDIM) bs[threadIdx.x] = b2[threadIdx.x];
    __syncthreads();

    int i = blockIdx.x * blockDim.x + threadIdx.x;
    if (i >= N) return;

    float dv = rsqrtf((float)(g_deg[i] + 1));
    float row[HDIM];
    #pragma unroll
    for (int c = 0; c < 2; c++) {
        uint4 a = g_agg2[(size_t)i * 2 + c];
        float2 f0 = __half22float2(*(__half2*)&a.x);
        float2 f1 = __half22float2(*(__half2*)&a.y);
        float2 f2v = __half22float2(*(__half2*)&a.z);
        float2 f3 = __half22float2(*(__half2*)&a.w);
        row[c * 8 + 0] = f0.x * dv; row[c * 8 + 1] = f0.y * dv;
        row[c * 8 + 2] = f1.x * dv; row[c * 8 + 3] = f1.y * dv;
        row[c * 8 + 4] = f2v.x * dv; row[c * 8 + 5] = f2v.y * dv;
        row[c * 8 + 6] = f3.x * dv; row[c * 8 + 7] = f3.y * dv;
    }

    float logit[CDIM];
    #pragma unroll
    for (int j = 0; j < CDIM; j++) logit[j] = bs[j];
    #pragma unroll
    for (int k = 0; k < HDIM; k++) {
        float v = row[k];
        const float* wr = &w[k * CDIM];
        #pragma unroll
        for (int j = 0; j < CDIM; j++) logit[j] += v * wr[j];
    }

    float mx = logit[0];
    #pragma unroll
    for (int j = 1; j < CDIM; j++) mx = fmaxf(mx, logit[j]);
    float sum = 0.0f;
    #pragma unroll
    for (int j = 0; j < CDIM; j++) sum += __expf(logit[j] - mx);
    float inv = 1.0f / sum;

    float* so = dout + (size_t)i * CDIM;
    #pragma unroll
    for (int j = 0; j < CDIM; j++) so[j] = __expf(logit[j] - mx) * inv;

    if (write_h) {
        float* ho = dout + (size_t)N * CDIM + (size_t)i * CDIM;
        #pragma unroll
        for (int j = 0; j < CDIM; j++) ho[j] = logit[j];
    }
}

// ---------------------------------------------------------------
extern "C" void kernel_launch(void* const* d_in, const int* in_sizes, int n_in,
                              void* d_out, int out_size)
{
    // metadata order: x, edge_index, num_nodes, W1, b1, W2, b2
    const float* x  = (const float*)d_in[0];
    const void*  ei = d_in[1];
    const float* W1 = (const float*)d_in[3];
    const float* b1 = (const float*)d_in[4];
    const float* W2 = (const float*)d_in[5];
    const float* b2 = (const float*)d_in[6];
    float* out = (float*)d_out;

    int N = in_sizes[0] / FDIM;
    int E = in_sizes[1] / 2;
    if (N > NMAX) N = NMAX;
    if (E > EMAX) E = EMAX;
    int write_h = (out_size >= 2 * N * CDIM) ? 1 : 0;

    const int B = 256;

    // Fork-join: edge processing (L2/atomic-bound) runs concurrently
    // with the tensor-core GEMM (DRAM-bound) on a second stream.
    cudaStream_t s2;
    cudaEvent_t evFork, evJoin;
    cudaStreamCreateWithFlags(&s2, cudaStreamNonBlocking);
    cudaEventCreateWithFlags(&evFork, cudaEventDisableTiming);
    cudaEventCreateWithFlags(&evJoin, cudaEventDisableTiming);

    cudaEventRecord(evFork, 0);
    cudaStreamWaitEvent(s2, evFork, 0);

    // branch B (s2): raw GEMM via HMMA, independent of edges
    k_gemm_mma<<<(N + 127) / 128, 256, 0, s2>>>(x, W1, N);
    cudaEventRecord(evJoin, s2);

    // branch A (main stream): edge decode + degree
    k_init<<<(N + B - 1) / B, B>>>((const int*)ei, N);
    k_convert<<<(E + B - 1) / B, B>>>(ei, E);

    // join
    cudaStreamWaitEvent(0, evJoin, 0);

    k_scale<<<(N * 8 + B - 1) / B, B>>>(N);

    k_prop<<<((size_t)E * 2 + B - 1) / B, B>>>(E, 0);
    k_mid<<<(N * 2 + B - 1) / B, B>>>(b1, N);
    k_prop<<<((size_t)E * 2 + B - 1) / B, B>>>(E, 1);

    k_out<<<(N + B - 1) / B, B>>>(W2, b2, out, N, write_h);

    cudaStreamDestroy(s2);
    cudaEventDestroy(evFork);
    cudaEventDestroy(evJoin);
}

// round 17
// speedup vs baseline: 1.2729x; 1.0249x over previous
#include <cuda_runtime.h>
#include <cuda_fp16.h>
#include <cstdint>
#include <cstring>

// Problem constants: N=100000, F=512, H=16, C=40, E=3200000
#define NMAX 100000
#define EMAX 3200000
#define FDIM 512
#define HDIM 16
#define CDIM 40

// ---- scratch (static device globals; no allocation allowed) ----
__device__ int    g_is64;
__device__ int2   g_edge[EMAX];      // (src, dst)
__device__ int    g_deg[NMAX];
__device__ float2 g_hraw[NMAX * 8];  // fp32 raw x@W1 (pre-scale)
__device__ uint4  g_h   [NMAX * 2];  // fp16 scaled hidden L1 (gather table)
__device__ uint4  g_h2  [NMAX * 2];  // fp16 scaled hidden L2 (gather table)
__device__ uint4  g_agg1[NMAX * 2];  // fp16 accumulator L1 (init = g_h row)
__device__ uint4  g_agg2[NMAX * 2];  // fp16 accumulator L2 (init = g_h2 row)

// ---------------------------------------------------------------
__global__ void k_init(const int* __restrict__ ei, int N) {
    int i = blockIdx.x * blockDim.x + threadIdx.x;
    if (i < N) g_deg[i] = 0;
    if (i == 0) {
        int any = 0;
        #pragma unroll
        for (int q = 1; q < 256; q += 2) any |= ei[q];
        g_is64 = (any == 0) ? 1 : 0;
    }
}

// Normalize edges to packed int2 and count in-degree (dst side).
__global__ __launch_bounds__(256) void k_convert(const void* __restrict__ ei, int E) {
    int e = blockIdx.x * blockDim.x + threadIdx.x;
    if (e >= E) return;
    int s, d;
    if (g_is64) {
        const long long* p = (const long long*)ei;
        s = (int)p[e];
        d = (int)p[(long long)E + e];
    } else {
        const int* p = (const int*)ei;
        s = p[e];
        d = p[E + e];
    }
    g_edge[e] = make_int2(s, d);
    atomicAdd(&g_deg[d], 1);
}

// ---------------------------------------------------------------
// Tensor-core GEMM1 (raw): g_hraw[i,:] = x[i,:] @ W1.
//   D = xh@Wh + xh@Wl      (x quantized to fp16; W kept hi+lo exact)
// The xl residual path (R15/R16) is dropped: the conversion stream
// was the issue bottleneck, and x-quantization error (~2.8e-4 RMS)
// adds in quadrature to the existing 7.6e-4 -> ~8.1e-4 < 1e-3 gate.
// Depth-2 software pipeline on the x loads retained.
// Fragment layout identical to R15/R16 (verified correct).
#define WT_PITCH 520
#define MMA16816(d, a0, a1, a2, a3, b0, b1) \
    asm volatile("mma.sync.aligned.m16n8k16.row.col.f32.f16.f16.f32 " \
        "{%0,%1,%2,%3}, {%4,%5,%6,%7}, {%8,%9}, {%0,%1,%2,%3};" \
        : "+f"((d)[0]), "+f"((d)[1]), "+f"((d)[2]), "+f"((d)[3]) \
        : "r"(a0), "r"(a1), "r"(a2), "r"(a3), "r"(b0), "r"(b1))

__device__ __forceinline__ uint32_t h2u(__half2 h) {
    uint32_t u; memcpy(&u, &h, 4); return u;
}

__global__ __launch_bounds__(256) void k_gemm_mma(
    const float* __restrict__ x, const float* __restrict__ W1, int N)
{
    __shared__ __half sWh[16 * WT_PITCH];
    __shared__ __half sWl[16 * WT_PITCH];
    // W1 is [512][16] row-major. Store transposed: Wt[n][k].
    for (int idx = threadIdx.x; idx < FDIM * HDIM; idx += 256) {
        int k = idx >> 4, n = idx & 15;
        float w = W1[idx];
        __half wh = __float2half_rn(w);
        sWh[n * WT_PITCH + k] = wh;
        sWl[n * WT_PITCH + k] = __float2half_rn(w - __half2float(wh));
    }
    __syncthreads();

    int warp = threadIdx.x >> 5;
    int lane = threadIdx.x & 31;
    int g = lane >> 2;
    int tc = lane & 3;
    int rowBase = blockIdx.x * 128 + warp * 16;
    if (rowBase >= N) return;    // N % 16 == 0: warps all-or-nothing

    const float* xp0 = x + (size_t)(rowBase + g) * FDIM;
    const float* xp8 = x + (size_t)(rowBase + g + 8) * FDIM;

    float d0[4] = {0.f, 0.f, 0.f, 0.f};
    float d1[4] = {0.f, 0.f, 0.f, 0.f};

    // depth-2 prefetch buffer: buf[parity][0..3]
    float2 buf[2][4];
    #pragma unroll
    for (int p = 0; p < 2; p++) {
        int c = p * 16 + tc * 2;
        buf[p][0] = *(const float2*)(xp0 + c);
        buf[p][1] = *(const float2*)(xp8 + c);
        buf[p][2] = *(const float2*)(xp0 + c + 8);
        buf[p][3] = *(const float2*)(xp8 + c + 8);
    }

    #pragma unroll 4
    for (int ks = 0; ks < 32; ks++) {
        int par = ks & 1;
        float2 p00 = buf[par][0];
        float2 p80 = buf[par][1];
        float2 p01 = buf[par][2];
        float2 p81 = buf[par][3];

        // issue loads for step ks+2 before any convert/MMA work
        if (ks + 2 < 32) {
            int cn = (ks + 2) * 16 + tc * 2;
            buf[par][0] = *(const float2*)(xp0 + cn);
            buf[par][1] = *(const float2*)(xp8 + cn);
            buf[par][2] = *(const float2*)(xp0 + cn + 8);
            buf[par][3] = *(const float2*)(xp8 + cn + 8);
        }

        int c = ks * 16 + tc * 2;

        uint32_t ah0 = h2u(__floats2half2_rn(p00.x, p00.y));
        uint32_t ah1 = h2u(__floats2half2_rn(p80.x, p80.y));
        uint32_t ah2 = h2u(__floats2half2_rn(p01.x, p01.y));
        uint32_t ah3 = h2u(__floats2half2_rn(p81.x, p81.y));

        #pragma unroll
        for (int j = 0; j < 2; j++) {
            int n = j * 8 + g;
            const __half* bh = &sWh[n * WT_PITCH + c];
            const __half* bl = &sWl[n * WT_PITCH + c];
            uint32_t bh0 = *(const uint32_t*)bh;
            uint32_t bh1 = *(const uint32_t*)(bh + 8);
            uint32_t bl0 = *(const uint32_t*)bl;
            uint32_t bl1 = *(const uint32_t*)(bl + 8);
            float* dd = j ? d1 : d0;
            MMA16816(dd, ah0, ah1, ah2, ah3, bh0, bh1);   // xh @ Wh
            MMA16816(dd, ah0, ah1, ah2, ah3, bl0, bl1);   // xh @ Wl
        }
    }

    int r0 = rowBase + g, r8 = rowBase + g + 8;
    g_hraw[(size_t)r0 * 8 + 0 + tc] = make_float2(d0[0], d0[1]);
    g_hraw[(size_t)r8 * 8 + 0 + tc] = make_float2(d0[2], d0[3]);
    g_hraw[(size_t)r0 * 8 + 4 + tc] = make_float2(d1[0], d1[1]);
    g_hraw[(size_t)r8 * 8 + 4 + tc] = make_float2(d1[2], d1[3]);
}

// ---------------------------------------------------------------
// Scale epilogue (after join): hs = fp16(dinv * hraw), dinv computed
// inline from deg. Writes gather table g_h and accumulator init g_agg1.
__global__ void k_scale(int N) {
    int idx = blockIdx.x * blockDim.x + threadIdx.x;   // half2 index
    if (idx >= N * 8) return;
    int i = idx >> 3;
    float dv = rsqrtf((float)(g_deg[i] + 1));
    float2 rf = g_hraw[idx];
    rf.x *= dv; rf.y *= dv;
    __half2 hv = __float22half2_rn(rf);
    ((__half2*)g_h)[idx] = hv;
    ((__half2*)g_agg1)[idx] = hv;
}

// ---------------------------------------------------------------
// Edge propagation: 2 threads per edge, one 16B chunk (8 halves) each.
// (FROZEN R10 shape.)
__global__ __launch_bounds__(256) void k_prop(int E, int layer) {
    int t = blockIdx.x * blockDim.x + threadIdx.x;
    int e = t >> 1;
    if (e >= E) return;
    int c = t & 1;
    const uint4* hin = layer ? g_h2 : g_h;
    uint4* out = layer ? g_agg2 : g_agg1;

    int2 sd = g_edge[e];
    uint4 v = hin[(size_t)sd.x * 2 + c];
    uint4* p = out + (size_t)sd.y * 2 + c;
    asm volatile("red.global.add.noftz.v4.f16x2 [%0], {%1, %2, %3, %4};"
                 :: "l"(p), "r"(v.x), "r"(v.y), "r"(v.z), "r"(v.w)
                 : "memory");
}

// ---------------------------------------------------------------
// Mid layer, per 16B chunk: out1 = relu(dinv*agg1 + b1); hs2 = dinv*out1
// writes g_h2 (gather table) and g_agg2 (self-loop init), both fp16.
__global__ void k_mid(const float* __restrict__ b1, int N) {
    int idx = blockIdx.x * blockDim.x + threadIdx.x;   // chunk index
    if (idx >= N * 2) return;
    int i = idx >> 1;
    int c = idx & 1;
    float dv = rsqrtf((float)(g_deg[i] + 1));
    uint4 a = g_agg1[idx];
    float2 f0 = __half22float2(*(__half2*)&a.x);
    float2 f1 = __half22float2(*(__half2*)&a.y);
    float2 f2v = __half22float2(*(__half2*)&a.z);
    float2 f3 = __half22float2(*(__half2*)&a.w);
    const float4* b4 = (const float4*)b1;
    float4 bb0 = b4[c * 2 + 0];
    float4 bb1 = b4[c * 2 + 1];
    float2 r0, r1, r2, r3;
    r0.x = fmaxf(dv * f0.x + bb0.x, 0.f) * dv;
    r0.y = fmaxf(dv * f0.y + bb0.y, 0.f) * dv;
    r1.x = fmaxf(dv * f1.x + bb0.z, 0.f) * dv;
    r1.y = fmaxf(dv * f1.y + bb0.w, 0.f) * dv;
    r2.x = fmaxf(dv * f2v.x + bb1.x, 0.f) * dv;
    r2.y = fmaxf(dv * f2v.y + bb1.y, 0.f) * dv;
    r3.x = fmaxf(dv * f3.x + bb1.z, 0.f) * dv;
    r3.y = fmaxf(dv * f3.y + bb1.w, 0.f) * dv;
    uint4 o;
    *(__half2*)&o.x = __float22half2_rn(r0);
    *(__half2*)&o.y = __float22half2_rn(r1);
    *(__half2*)&o.z = __float22half2_rn(r2);
    *(__half2*)&o.w = __float22half2_rn(r3);
    g_h2[idx] = o;
    g_agg2[idx] = o;
}

// ---------------------------------------------------------------
// Output: logits = (dinv[i]*agg2[i,:]) @ W2 + b2 ; out = softmax
// d_out[0:N*40) = softmax ; d_out[N*40:2N*40) = logits
__global__ __launch_bounds__(256) void k_out(
    const float* __restrict__ W2, const float* __restrict__ b2,
    float* __restrict__ dout, int N, int write_h)
{
    __shared__ float w[HDIM * CDIM];
    __shared__ float bs[CDIM];
    for (int i = threadIdx.x; i < HDIM * CDIM; i += blockDim.x) w[i] = W2[i];
    if (threadIdx.x < CDIM) bs[threadIdx.x] = b2[threadIdx.x];
    __syncthreads();

    int i = blockIdx.x * blockDim.x + threadIdx.x;
    if (i >= N) return;

    float dv = rsqrtf((float)(g_deg[i] + 1));
    float row[HDIM];
    #pragma unroll
    for (int c = 0; c < 2; c++) {
        uint4 a = g_agg2[(size_t)i * 2 + c];
        float2 f0 = __half22float2(*(__half2*)&a.x);
        float2 f1 = __half22float2(*(__half2*)&a.y);
        float2 f2v = __half22float2(*(__half2*)&a.z);
        float2 f3 = __half22float2(*(__half2*)&a.w);
        row[c * 8 + 0] = f0.x * dv; row[c * 8 + 1] = f0.y * dv;
        row[c * 8 + 2] = f1.x * dv; row[c * 8 + 3] = f1.y * dv;
        row[c * 8 + 4] = f2v.x * dv; row[c * 8 + 5] = f2v.y * dv;
        row[c * 8 + 6] = f3.x * dv; row[c * 8 + 7] = f3.y * dv;
    }

    float logit[CDIM];
    #pragma unroll
    for (int j = 0; j < CDIM; j++) logit[j] = bs[j];
    #pragma unroll
    for (int k = 0; k < HDIM; k++) {
        float v = row[k];
        const float* wr = &w[k * CDIM];
        #pragma unroll
        for (int j = 0; j < CDIM; j++) logit[j] += v * wr[j];
    }

    float mx = logit[0];
    #pragma unroll
    for (int j = 1; j < CDIM; j++) mx = fmaxf(mx, logit[j]);
    float sum = 0.0f;
    #pragma unroll
    for (int j = 0; j < CDIM; j++) sum += __expf(logit[j] - mx);
    float inv = 1.0f / sum;

    float* so = dout + (size_t)i * CDIM;
    #pragma unroll
    for (int j = 0; j < CDIM; j++) so[j] = __expf(logit[j] - mx) * inv;

    if (write_h) {
        float* ho = dout + (size_t)N * CDIM + (size_t)i * CDIM;
        #pragma unroll
        for (int j = 0; j < CDIM; j++) ho[j] = logit[j];
    }
}

// ---------------------------------------------------------------
extern "C" void kernel_launch(void* const* d_in, const int* in_sizes, int n_in,
                              void* d_out, int out_size)
{
    // metadata order: x, edge_index, num_nodes, W1, b1, W2, b2
    const float* x  = (const float*)d_in[0];
    const void*  ei = d_in[1];
    const float* W1 = (const float*)d_in[3];
    const float* b1 = (const float*)d_in[4];
    const float* W2 = (const float*)d_in[5];
    const float* b2 = (const float*)d_in[6];
    float* out = (float*)d_out;

    int N = in_sizes[0] / FDIM;
    int E = in_sizes[1] / 2;
    if (N > NMAX) N = NMAX;
    if (E > EMAX) E = EMAX;
    int write_h = (out_size >= 2 * N * CDIM) ? 1 : 0;

    const int B = 256;

    // Fork-join: edge processing (L2/atomic-bound) runs concurrently
    // with the tensor-core GEMM on a second stream.
    cudaStream_t s2;
    cudaEvent_t evFork, evJoin;
    cudaStreamCreateWithFlags(&s2, cudaStreamNonBlocking);
    cudaEventCreateWithFlags(&evFork, cudaEventDisableTiming);
    cudaEventCreateWithFlags(&evJoin, cudaEventDisableTiming);

    cudaEventRecord(evFork, 0);
    cudaStreamWaitEvent(s2, evFork, 0);

    // branch B (s2): raw GEMM via HMMA, independent of edges
    k_gemm_mma<<<(N + 127) / 128, 256, 0, s2>>>(x, W1, N);
    cudaEventRecord(evJoin, s2);

    // branch A (main stream): edge decode + degree
    k_init<<<(N + B - 1) / B, B>>>((const int*)ei, N);
    k_convert<<<(E + B - 1) / B, B>>>(ei, E);

    // join
    cudaStreamWaitEvent(0, evJoin, 0);

    k_scale<<<(N * 8 + B - 1) / B, B>>>(N);

    k_prop<<<((size_t)E * 2 + B - 1) / B, B>>>(E, 0);
    k_mid<<<(N * 2 + B - 1) / B, B>>>(b1, N);
    k_prop<<<((size_t)E * 2 + B - 1) / B, B>>>(E, 1);

    k_out<<<(N + B - 1) / B, B>>>(W2, b2, out, N, write_h);

    cudaStreamDestroy(s2);
    cudaEventDestroy(evFork);
    cudaEventDestroy(evJoin);
}